// round 1
// baseline (speedup 1.0000x reference)
#include <cuda_runtime.h>

#define Bb 32
#define Ll 512
#define Cc 512
#define Hh 8
#define DHd 64
#define BHn (Bb*Hh)      // 256
#define MTOT (Bb*Ll)     // 16384
#define LN_EPS 1e-5f
#define SCALE 0.04419417382415922f  // 512^-0.5 (full C, as in source)

// Scratch (device globals: allocation-guard-safe)
__device__ float g_q[(size_t)BHn * Ll * DHd];
__device__ float g_k[(size_t)BHn * Ll * DHd];
__device__ float g_v[(size_t)BHn * Ll * DHd];
__device__ float g_s[(size_t)BHn * Ll * Ll];     // scores -> attn (in place)
__device__ float g_preln[(size_t)MTOT * Cc];

// ---------------------------------------------------------------------------
// Kernel 1: fused QKV projection. Y = X @ W^T, output in (B,H,L,DH) layout.
// M=16384, N=512, K=512. 64x64 tile, BK=16, 256 threads, 4x4 per thread.
// ---------------------------------------------------------------------------
__global__ __launch_bounds__(256) void qkv_kernel(
    const float* __restrict__ x, const float* __restrict__ wq,
    const float* __restrict__ wk, const float* __restrict__ wv)
{
    __shared__ float As[16][64];
    __shared__ float Bs[16][64];
    const int which = blockIdx.z;
    const float* __restrict__ w = (which == 0) ? wq : (which == 1) ? wk : wv;
    float* __restrict__ out = (which == 0) ? g_q : (which == 1) ? g_k : g_v;

    const int tid = threadIdx.x;
    const int tx = tid & 15, ty = tid >> 4;
    const int m0 = blockIdx.y << 6;
    const int n0 = blockIdx.x << 6;
    const int lrow = tid >> 2;        // 0..63
    const int lk = (tid & 3) << 2;    // 0,4,8,12

    float acc[4][4];
#pragma unroll
    for (int i = 0; i < 4; i++)
#pragma unroll
        for (int j = 0; j < 4; j++) acc[i][j] = 0.f;

    for (int k0 = 0; k0 < 512; k0 += 16) {
        float4 av = *(const float4*)(x + (size_t)(m0 + lrow) * 512 + k0 + lk);
        float4 bv = *(const float4*)(w + (size_t)(n0 + lrow) * 512 + k0 + lk);
        As[lk + 0][lrow] = av.x; As[lk + 1][lrow] = av.y;
        As[lk + 2][lrow] = av.z; As[lk + 3][lrow] = av.w;
        Bs[lk + 0][lrow] = bv.x; Bs[lk + 1][lrow] = bv.y;
        Bs[lk + 2][lrow] = bv.z; Bs[lk + 3][lrow] = bv.w;
        __syncthreads();
#pragma unroll
        for (int kk = 0; kk < 16; kk++) {
            float4 a = *(const float4*)&As[kk][ty << 2];
            float4 b = *(const float4*)&Bs[kk][tx << 2];
            float ar[4] = {a.x, a.y, a.z, a.w};
            float br[4] = {b.x, b.y, b.z, b.w};
#pragma unroll
            for (int i = 0; i < 4; i++)
#pragma unroll
                for (int j = 0; j < 4; j++) acc[i][j] += ar[i] * br[j];
        }
        __syncthreads();
    }
#pragma unroll
    for (int i = 0; i < 4; i++) {
        int m = m0 + (ty << 2) + i;
        int b = m >> 9, l = m & 511;
#pragma unroll
        for (int j = 0; j < 4; j++) {
            int n = n0 + (tx << 2) + j;
            int h = n >> 6, d = n & 63;
            out[(((size_t)(b * Hh + h)) * Ll + l) * DHd + d] = acc[i][j];
        }
    }
}

// ---------------------------------------------------------------------------
// Kernel 2: batched S = Q @ K^T * scale per (b,h). M=N=512, K=64.
// ---------------------------------------------------------------------------
__global__ __launch_bounds__(256) void scores_kernel()
{
    __shared__ float As[16][64];
    __shared__ float Bs[16][64];
    const int bh = blockIdx.z;
    const float* __restrict__ Q  = g_q + (size_t)bh * Ll * DHd;
    const float* __restrict__ Kp = g_k + (size_t)bh * Ll * DHd;
    float* __restrict__ S = g_s + (size_t)bh * Ll * Ll;

    const int tid = threadIdx.x;
    const int tx = tid & 15, ty = tid >> 4;
    const int m0 = blockIdx.y << 6;
    const int n0 = blockIdx.x << 6;
    const int lrow = tid >> 2;
    const int lk = (tid & 3) << 2;

    float acc[4][4];
#pragma unroll
    for (int i = 0; i < 4; i++)
#pragma unroll
        for (int j = 0; j < 4; j++) acc[i][j] = 0.f;

#pragma unroll
    for (int k0 = 0; k0 < 64; k0 += 16) {
        float4 av = *(const float4*)(Q  + (size_t)(m0 + lrow) * 64 + k0 + lk);
        float4 bv = *(const float4*)(Kp + (size_t)(n0 + lrow) * 64 + k0 + lk);
        As[lk + 0][lrow] = av.x; As[lk + 1][lrow] = av.y;
        As[lk + 2][lrow] = av.z; As[lk + 3][lrow] = av.w;
        Bs[lk + 0][lrow] = bv.x; Bs[lk + 1][lrow] = bv.y;
        Bs[lk + 2][lrow] = bv.z; Bs[lk + 3][lrow] = bv.w;
        __syncthreads();
#pragma unroll
        for (int kk = 0; kk < 16; kk++) {
            float4 a = *(const float4*)&As[kk][ty << 2];
            float4 b = *(const float4*)&Bs[kk][tx << 2];
            float ar[4] = {a.x, a.y, a.z, a.w};
            float br[4] = {b.x, b.y, b.z, b.w};
#pragma unroll
            for (int i = 0; i < 4; i++)
#pragma unroll
                for (int j = 0; j < 4; j++) acc[i][j] += ar[i] * br[j];
        }
        __syncthreads();
    }
#pragma unroll
    for (int i = 0; i < 4; i++) {
        int m = m0 + (ty << 2) + i;
#pragma unroll
        for (int j = 0; j < 4; j++) {
            int n = n0 + (tx << 2) + j;
            S[(size_t)m * Ll + n] = acc[i][j] * SCALE;
        }
    }
}

// ---------------------------------------------------------------------------
// Kernel 3: per-row softmax + POST-softmax relative bias add (in place).
// rel_index[q][k] = k - q + (L-1); bias_table is (2L-1, H).
// ---------------------------------------------------------------------------
__global__ __launch_bounds__(256) void softmax_bias_kernel(
    const float* __restrict__ bias_table)
{
    const int q  = blockIdx.x;
    const int bh = blockIdx.y;
    const int h  = bh & (Hh - 1);
    float* __restrict__ row = g_s + ((size_t)bh * Ll + q) * Ll;
    const int t = threadIdx.x;

    float v0 = row[t], v1 = row[t + 256];

    __shared__ float redm[8];
    __shared__ float reds[8];

    float m = fmaxf(v0, v1);
#pragma unroll
    for (int o = 16; o > 0; o >>= 1) m = fmaxf(m, __shfl_xor_sync(0xffffffffu, m, o));
    if ((t & 31) == 0) redm[t >> 5] = m;
    __syncthreads();
    float mall = redm[0];
#pragma unroll
    for (int i = 1; i < 8; i++) mall = fmaxf(mall, redm[i]);

    float e0 = __expf(v0 - mall);
    float e1 = __expf(v1 - mall);
    float s = e0 + e1;
#pragma unroll
    for (int o = 16; o > 0; o >>= 1) s += __shfl_xor_sync(0xffffffffu, s, o);
    if ((t & 31) == 0) reds[t >> 5] = s;
    __syncthreads();
    float sall = reds[0];
#pragma unroll
    for (int i = 1; i < 8; i++) sall += reds[i];
    float inv = 1.f / sall;

    int k0 = t, k1 = t + 256;
    row[k0] = e0 * inv + bias_table[(size_t)(k0 - q + (Ll - 1)) * Hh + h];
    row[k1] = e1 * inv + bias_table[(size_t)(k1 - q + (Ll - 1)) * Hh + h];
}

// ---------------------------------------------------------------------------
// Kernel 4: batched O = attn @ V per (b,h). M=512, N=64, K=512.
// Writes pre-LN buffer in (B, L, C) layout.
// ---------------------------------------------------------------------------
__global__ __launch_bounds__(256) void pv_kernel()
{
    __shared__ float As[16][64];
    __shared__ float Bs[16][64];
    const int bh = blockIdx.y;
    const int b = bh >> 3, h = bh & 7;
    const float* __restrict__ Ap = g_s + (size_t)bh * Ll * Ll;
    const float* __restrict__ V  = g_v + (size_t)bh * Ll * DHd;
    const int m0 = blockIdx.x << 6;

    const int tid = threadIdx.x;
    const int tx = tid & 15, ty = tid >> 4;
    const int lrow = tid >> 2;          // A: 0..63
    const int lk = (tid & 3) << 2;      // A: 0,4,8,12
    const int vrow = tid >> 4;          // B: 0..15
    const int vcol = (tid & 15) << 2;   // B: 0..60

    float acc[4][4];
#pragma unroll
    for (int i = 0; i < 4; i++)
#pragma unroll
        for (int j = 0; j < 4; j++) acc[i][j] = 0.f;

    for (int k0 = 0; k0 < 512; k0 += 16) {
        float4 av = *(const float4*)(Ap + (size_t)(m0 + lrow) * 512 + k0 + lk);
        float4 bv = *(const float4*)(V + (size_t)(k0 + vrow) * 64 + vcol);
        As[lk + 0][lrow] = av.x; As[lk + 1][lrow] = av.y;
        As[lk + 2][lrow] = av.z; As[lk + 3][lrow] = av.w;
        *(float4*)&Bs[vrow][vcol] = bv;
        __syncthreads();
#pragma unroll
        for (int kk = 0; kk < 16; kk++) {
            float4 a = *(const float4*)&As[kk][ty << 2];
            float4 b2 = *(const float4*)&Bs[kk][tx << 2];
            float ar[4] = {a.x, a.y, a.z, a.w};
            float br[4] = {b2.x, b2.y, b2.z, b2.w};
#pragma unroll
            for (int i = 0; i < 4; i++)
#pragma unroll
                for (int j = 0; j < 4; j++) acc[i][j] += ar[i] * br[j];
        }
        __syncthreads();
    }
#pragma unroll
    for (int i = 0; i < 4; i++) {
        int m = m0 + (ty << 2) + i;            // q position
#pragma unroll
        for (int j = 0; j < 4; j++) {
            int n = (tx << 2) + j;             // d
            g_preln[((size_t)(b * Ll) + m) * Cc + h * DHd + n] = acc[i][j];
        }
    }
}

// ---------------------------------------------------------------------------
// Kernel 5: LayerNorm over C=512.
// ---------------------------------------------------------------------------
__global__ __launch_bounds__(256) void ln_kernel(
    const float* __restrict__ gamma, const float* __restrict__ beta,
    float* __restrict__ out)
{
    const int row = blockIdx.x;
    const float* __restrict__ p = g_preln + (size_t)row * Cc;
    const int t = threadIdx.x;

    float v0 = p[t], v1 = p[t + 256];

    __shared__ float red[8];

    float s = v0 + v1;
#pragma unroll
    for (int o = 16; o > 0; o >>= 1) s += __shfl_xor_sync(0xffffffffu, s, o);
    if ((t & 31) == 0) red[t >> 5] = s;
    __syncthreads();
    float tot = red[0];
#pragma unroll
    for (int i = 1; i < 8; i++) tot += red[i];
    float mu = tot * (1.f / 512.f);

    float d0 = v0 - mu, d1 = v1 - mu;
    float sq = d0 * d0 + d1 * d1;
    __syncthreads();
#pragma unroll
    for (int o = 16; o > 0; o >>= 1) sq += __shfl_xor_sync(0xffffffffu, sq, o);
    if ((t & 31) == 0) red[t >> 5] = sq;
    __syncthreads();
    float totsq = red[0];
#pragma unroll
    for (int i = 1; i < 8; i++) totsq += red[i];
    float var = totsq * (1.f / 512.f);
    float inv = rsqrtf(var + LN_EPS);

    out[(size_t)row * Cc + t]       = gamma[t]       * d0 * inv + beta[t];
    out[(size_t)row * Cc + t + 256] = gamma[t + 256] * d1 * inv + beta[t + 256];
}

// ---------------------------------------------------------------------------
extern "C" void kernel_launch(void* const* d_in, const int* in_sizes, int n_in,
                              void* d_out, int out_size)
{
    const float* x          = (const float*)d_in[0];
    const float* wq         = (const float*)d_in[1];
    const float* wk         = (const float*)d_in[2];
    const float* wv         = (const float*)d_in[3];
    const float* bias_table = (const float*)d_in[4];
    const float* gamma      = (const float*)d_in[5];
    const float* beta       = (const float*)d_in[6];
    // d_in[7] = rel_index (int32) — index is analytic (k - q + L - 1), unused.
    float* out = (float*)d_out;

    qkv_kernel<<<dim3(8, 256, 3), 256>>>(x, wq, wk, wv);
    scores_kernel<<<dim3(8, 8, 256), 256>>>();
    softmax_bias_kernel<<<dim3(512, 256), 256>>>(bias_table);
    pv_kernel<<<dim3(8, 256), 256>>>();
    ln_kernel<<<dim3(16384), 256>>>(gamma, beta, out);
}

// round 3
// speedup vs baseline: 2.7111x; 2.7111x over previous
#include <cuda_runtime.h>
#include <cstdint>

#define Ll 512
#define Hh 8
#define LN_EPS 1e-5f
#define SCALE 0.04419417382415922f  // 512^-0.5 (full C, as in source)

// ---------------- scratch (device globals: allocation-guard-safe) ----------
__device__ float g_q[(size_t)256 * 512 * 64];    // (b,h,l,d) tf32-rounded
__device__ float g_k[(size_t)256 * 512 * 64];    // (b,h,l,d) tf32-rounded
__device__ float g_v[(size_t)256 * 512 * 64];    // (b,h,l,d) tf32-rounded
__device__ float g_s[(size_t)256 * 512 * 512];   // scores -> P
__device__ float g_preln[(size_t)16384 * 512];

// ---------------- helpers ---------------------------------------------------
__device__ __forceinline__ uint32_t s2u(const void* p) {
    uint32_t a;
    asm("{ .reg .u64 t; cvta.to.shared.u64 t, %1; cvt.u32.u64 %0, t; }" : "=r"(a) : "l"(p));
    return a;
}
__device__ __forceinline__ float rna_tf32(float v) {
    uint32_t t; asm("cvt.rna.tf32.f32 %0, %1;" : "=r"(t) : "f"(v));
    return __uint_as_float(t);
}
__device__ __forceinline__ uint32_t rna_tf32_u(float v) {
    uint32_t t; asm("cvt.rna.tf32.f32 %0, %1;" : "=r"(t) : "f"(v));
    return t;
}
__device__ __forceinline__ void cpa16(uint32_t s, const void* g) {
    asm volatile("cp.async.cg.shared.global [%0], [%1], 16;" :: "r"(s), "l"(g));
}
__device__ __forceinline__ void cpa_commit() { asm volatile("cp.async.commit_group;" ::: "memory"); }
template <int N>
__device__ __forceinline__ void cpa_wait() { asm volatile("cp.async.wait_group %0;" :: "n"(N) : "memory"); }

__device__ __forceinline__ void mma8(float (&c)[4], const uint32_t (&a)[4], const uint32_t (&b)[2]) {
    asm volatile(
        "mma.sync.aligned.m16n8k8.row.col.f32.tf32.tf32.f32 "
        "{%0,%1,%2,%3}, {%4,%5,%6,%7}, {%8,%9}, {%0,%1,%2,%3};"
        : "+f"(c[0]), "+f"(c[1]), "+f"(c[2]), "+f"(c[3])
        : "r"(a[0]), "r"(a[1]), "r"(a[2]), "r"(a[3]), "r"(b[0]), "r"(b[1]));
}

// ---------------- generic tf32 mma mainloop ---------------------------------
// CTA tile: 128 x N_T. 8 warps: wm = warp&1 (64-row half), wn = warp>>1
// (N_T/4-wide strip). A is K-major [m][k] (lda floats). B:
//   BNMAJ=false: K-major [n][k] rows (ldb floats)
//   BNMAJ=true : N-major [k][n] rows (ldb floats)  -- V consumed untransposed
// K chunk = 16. Smem A stride 20 floats, B stride 20 (K-major) / 72 (N-major):
// verified bank-conflict-free for the m16n8k8 fragment pattern.
template <int N_T, bool BNMAJ, bool RNA>
__device__ __forceinline__ void gemm_mainloop(
    const float* __restrict__ A, int lda,
    const float* __restrict__ B, int ldb,
    int NC, float* sm, float (&acc)[4][N_T / 32][4])
{
    constexpr int NI = N_T / 32;
    constexpr int A_F = 128 * 20;                       // 2560 floats
    constexpr int B_F = BNMAJ ? (16 * 72) : (N_T * 20);
    constexpr int STAGE = A_F + B_F;
    const int tid = threadIdx.x;
    const int lane = tid & 31, warp = tid >> 5;
    const int wm = warp & 1, wn = warp >> 1;
    const int g = lane >> 2, t4 = lane & 3;
    const uint32_t sbase = s2u(sm);

#pragma unroll
    for (int mi = 0; mi < 4; ++mi)
#pragma unroll
        for (int ni = 0; ni < NI; ++ni)
#pragma unroll
            for (int r = 0; r < 4; ++r) acc[mi][ni][r] = 0.f;

    auto load_chunk = [&](int c, int buf) {
        uint32_t sa = sbase + buf * STAGE * 4;
#pragma unroll
        for (int i = 0; i < 2; ++i) {
            int idx = tid + i * 256;
            int r = idx >> 2, ksg = idx & 3;
            cpa16(sa + (uint32_t)(r * 80 + ksg * 16),
                  A + (size_t)r * lda + c * 16 + ksg * 4);
        }
        uint32_t sb = sa + A_F * 4;
        if (BNMAJ) {
            int r = tid >> 4, cs = tid & 15;
            cpa16(sb + (uint32_t)(r * 288 + cs * 16),
                  B + (size_t)(c * 16 + r) * ldb + cs * 4);
        } else {
#pragma unroll
            for (int i = 0; i < N_T / 64; ++i) {
                int idx = tid + i * 256;
                int r = idx >> 2, ksg = idx & 3;
                cpa16(sb + (uint32_t)(r * 80 + ksg * 16),
                      B + (size_t)r * ldb + c * 16 + ksg * 4);
            }
        }
    };

    load_chunk(0, 0);
    cpa_commit();

    for (int c = 0; c < NC; ++c) {
        if (c + 1 < NC) load_chunk(c + 1, (c + 1) & 1);
        cpa_commit();
        cpa_wait<1>();
        __syncthreads();

        const float* As = sm + (c & 1) * STAGE;
        const float* Bs = As + A_F;

#pragma unroll
        for (int ks = 0; ks < 2; ++ks) {
            const int k = ks * 8;
            uint32_t af[4][4];
#pragma unroll
            for (int mi = 0; mi < 4; ++mi) {
                int mr = wm * 64 + mi * 16 + g;
                float x0 = As[mr * 20 + k + t4];
                float x1 = As[(mr + 8) * 20 + k + t4];
                float x2 = As[mr * 20 + k + t4 + 4];
                float x3 = As[(mr + 8) * 20 + k + t4 + 4];
                if (RNA) {
                    af[mi][0] = rna_tf32_u(x0); af[mi][1] = rna_tf32_u(x1);
                    af[mi][2] = rna_tf32_u(x2); af[mi][3] = rna_tf32_u(x3);
                } else {
                    af[mi][0] = __float_as_uint(x0); af[mi][1] = __float_as_uint(x1);
                    af[mi][2] = __float_as_uint(x2); af[mi][3] = __float_as_uint(x3);
                }
            }
            uint32_t bf[NI][2];
#pragma unroll
            for (int ni = 0; ni < NI; ++ni) {
                float y0, y1;
                if (BNMAJ) {
                    int n = wn * (N_T / 4) + ni * 8 + g;
                    y0 = Bs[(k + t4) * 72 + n];
                    y1 = Bs[(k + t4 + 4) * 72 + n];
                } else {
                    int nr = wn * (N_T / 4) + ni * 8 + g;
                    y0 = Bs[nr * 20 + k + t4];
                    y1 = Bs[nr * 20 + k + t4 + 4];
                }
                if (RNA) {
                    bf[ni][0] = rna_tf32_u(y0); bf[ni][1] = rna_tf32_u(y1);
                } else {
                    bf[ni][0] = __float_as_uint(y0); bf[ni][1] = __float_as_uint(y1);
                }
            }
#pragma unroll
            for (int mi = 0; mi < 4; ++mi)
#pragma unroll
                for (int ni = 0; ni < NI; ++ni) mma8(acc[mi][ni], af[mi], bf[ni]);
        }
        __syncthreads();
    }
}

// ---------------- Kernel 1: QKV projection (tf32 mma) ------------------------
// grid (4 n-tiles, 128 m-tiles, 3). M=16384, N=512, K=512. Y = X @ W^T.
// Output rounded to tf32, layout (b,h,l,d).
__global__ __launch_bounds__(256) void qkv_g(
    const float* __restrict__ x, const float* __restrict__ wq,
    const float* __restrict__ wk, const float* __restrict__ wv)
{
    __shared__ alignas(16) float sm[2 * (128 * 20 + 128 * 20)];
    const int which = blockIdx.z;
    const int m0 = blockIdx.y * 128;
    const int n0 = blockIdx.x * 128;
    const float* w = (which == 0) ? wq : (which == 1) ? wk : wv;
    float* out = (which == 0) ? g_q : (which == 1) ? g_k : g_v;

    float acc[4][4][4];
    gemm_mainloop<128, false, true>(x + (size_t)m0 * 512, 512,
                                    w + (size_t)n0 * 512, 512, 32, sm, acc);

    const int lane = threadIdx.x & 31, warp = threadIdx.x >> 5;
    const int wm = warp & 1, wn = warp >> 1;
    const int g = lane >> 2, t4 = lane & 3;
#pragma unroll
    for (int mi = 0; mi < 4; ++mi) {
#pragma unroll
        for (int ni = 0; ni < 4; ++ni) {
            int n = n0 + wn * 32 + ni * 8 + 2 * t4;
            int h = n >> 6, d = n & 63;
            int m = m0 + wm * 64 + mi * 16 + g;
            int b = m >> 9, l = m & 511;
            float2 v0 = make_float2(rna_tf32(acc[mi][ni][0]), rna_tf32(acc[mi][ni][1]));
            float2 v1 = make_float2(rna_tf32(acc[mi][ni][2]), rna_tf32(acc[mi][ni][3]));
            *(float2*)&out[(((size_t)(b * 8 + h)) * 512 + l) * 64 + d] = v0;
            *(float2*)&out[(((size_t)(b * 8 + h)) * 512 + l + 8) * 64 + d] = v1;
        }
    }
}

// ---------------- Kernel 2: S = Q K^T * scale --------------------------------
// grid (4 n, 4 m, 256 bh). M=N=512, K=64 per (b,h).
__global__ __launch_bounds__(256) void scores_g(void)
{
    __shared__ alignas(16) float sm[2 * (128 * 20 + 128 * 20)];
    const int bh = blockIdx.z;
    const int m0 = blockIdx.y * 128;
    const int n0 = blockIdx.x * 128;

    float acc[4][4][4];
    gemm_mainloop<128, false, false>(g_q + (size_t)bh * 32768 + (size_t)m0 * 64, 64,
                                     g_k + (size_t)bh * 32768 + (size_t)n0 * 64, 64,
                                     4, sm, acc);

    float* outb = g_s + (size_t)bh * 262144;
    const int lane = threadIdx.x & 31, warp = threadIdx.x >> 5;
    const int wm = warp & 1, wn = warp >> 1;
    const int g = lane >> 2, t4 = lane & 3;
#pragma unroll
    for (int mi = 0; mi < 4; ++mi) {
#pragma unroll
        for (int ni = 0; ni < 4; ++ni) {
            int n = n0 + wn * 32 + ni * 8 + 2 * t4;
            int m = m0 + wm * 64 + mi * 16 + g;
            float2 v0 = make_float2(acc[mi][ni][0] * SCALE, acc[mi][ni][1] * SCALE);
            float2 v1 = make_float2(acc[mi][ni][2] * SCALE, acc[mi][ni][3] * SCALE);
            *(float2*)&outb[(size_t)m * 512 + n] = v0;
            *(float2*)&outb[(size_t)(m + 8) * 512 + n] = v1;
        }
    }
}

// ---------------- Kernel 3: softmax + post-softmax bias (in place) -----------
__global__ __launch_bounds__(256) void softmax_bias_kernel(
    const float* __restrict__ bias_table)
{
    const int q = blockIdx.x;
    const int bh = blockIdx.y;
    const int h = bh & (Hh - 1);
    float* __restrict__ row = g_s + ((size_t)bh * Ll + q) * Ll;
    const int t = threadIdx.x;

    float v0 = row[t], v1 = row[t + 256];
    __shared__ float redm[8];
    __shared__ float reds[8];

    float m = fmaxf(v0, v1);
#pragma unroll
    for (int o = 16; o > 0; o >>= 1) m = fmaxf(m, __shfl_xor_sync(0xffffffffu, m, o));
    if ((t & 31) == 0) redm[t >> 5] = m;
    __syncthreads();
    float mall = redm[0];
#pragma unroll
    for (int i = 1; i < 8; i++) mall = fmaxf(mall, redm[i]);

    float e0 = __expf(v0 - mall);
    float e1 = __expf(v1 - mall);
    float s = e0 + e1;
#pragma unroll
    for (int o = 16; o > 0; o >>= 1) s += __shfl_xor_sync(0xffffffffu, s, o);
    if ((t & 31) == 0) reds[t >> 5] = s;
    __syncthreads();
    float sall = reds[0];
#pragma unroll
    for (int i = 1; i < 8; i++) sall += reds[i];
    float inv = 1.f / sall;

    int k0 = t, k1 = t + 256;
    row[k0] = rna_tf32(e0 * inv + bias_table[(size_t)(k0 - q + (Ll - 1)) * Hh + h]);
    row[k1] = rna_tf32(e1 * inv + bias_table[(size_t)(k1 - q + (Ll - 1)) * Hh + h]);
}

// ---------------- Kernel 4: O = P @ V ----------------------------------------
// grid (4 m, 256 bh). M=512, N=64, K=512 per (b,h). V consumed as [k][n].
__global__ __launch_bounds__(256) void pv_g(void)
{
    __shared__ alignas(16) float sm[2 * (128 * 20 + 16 * 72)];
    const int bh = blockIdx.y;
    const int m0 = blockIdx.x * 128;
    const int b = bh >> 3, h = bh & 7;

    float acc[4][2][4];
    gemm_mainloop<64, true, false>(g_s + (size_t)bh * 262144 + (size_t)m0 * 512, 512,
                                   g_v + (size_t)bh * 32768, 64, 32, sm, acc);

    const int lane = threadIdx.x & 31, warp = threadIdx.x >> 5;
    const int wm = warp & 1, wn = warp >> 1;
    const int g = lane >> 2, t4 = lane & 3;
#pragma unroll
    for (int mi = 0; mi < 4; ++mi) {
#pragma unroll
        for (int ni = 0; ni < 2; ++ni) {
            int n = wn * 16 + ni * 8 + 2 * t4;
            int m = m0 + wm * 64 + mi * 16 + g;
            float2 v0 = make_float2(acc[mi][ni][0], acc[mi][ni][1]);
            float2 v1 = make_float2(acc[mi][ni][2], acc[mi][ni][3]);
            *(float2*)&g_preln[((size_t)(b * 512) + m) * 512 + h * 64 + n] = v0;
            *(float2*)&g_preln[((size_t)(b * 512) + m + 8) * 512 + h * 64 + n] = v1;
        }
    }
}

// ---------------- Kernel 5: LayerNorm ----------------------------------------
__global__ __launch_bounds__(256) void ln_kernel(
    const float* __restrict__ gamma, const float* __restrict__ beta,
    float* __restrict__ out)
{
    const int row = blockIdx.x;
    const float* __restrict__ pr = g_preln + (size_t)row * 512;
    const int t = threadIdx.x;

    float v0 = pr[t], v1 = pr[t + 256];
    __shared__ float red[8];

    float s = v0 + v1;
#pragma unroll
    for (int o = 16; o > 0; o >>= 1) s += __shfl_xor_sync(0xffffffffu, s, o);
    if ((t & 31) == 0) red[t >> 5] = s;
    __syncthreads();
    float tot = red[0];
#pragma unroll
    for (int i = 1; i < 8; i++) tot += red[i];
    float mu = tot * (1.f / 512.f);

    float d0 = v0 - mu, d1 = v1 - mu;
    float sq = d0 * d0 + d1 * d1;
    __syncthreads();
#pragma unroll
    for (int o = 16; o > 0; o >>= 1) sq += __shfl_xor_sync(0xffffffffu, sq, o);
    if ((t & 31) == 0) red[t >> 5] = sq;
    __syncthreads();
    float totsq = red[0];
#pragma unroll
    for (int i = 1; i < 8; i++) totsq += red[i];
    float var = totsq * (1.f / 512.f);
    float inv = rsqrtf(var + LN_EPS);

    out[(size_t)row * 512 + t]       = gamma[t]       * d0 * inv + beta[t];
    out[(size_t)row * 512 + t + 256] = gamma[t + 256] * d1 * inv + beta[t + 256];
}

// ---------------------------------------------------------------------------
extern "C" void kernel_launch(void* const* d_in, const int* in_sizes, int n_in,
                              void* d_out, int out_size)
{
    const float* x          = (const float*)d_in[0];
    const float* wq         = (const float*)d_in[1];
    const float* wk         = (const float*)d_in[2];
    const float* wv         = (const float*)d_in[3];
    const float* bias_table = (const float*)d_in[4];
    const float* gamma      = (const float*)d_in[5];
    const float* beta       = (const float*)d_in[6];
    float* out = (float*)d_out;

    qkv_g<<<dim3(4, 128, 3), 256>>>(x, wq, wk, wv);
    scores_g<<<dim3(4, 4, 256), 256>>>();
    softmax_bias_kernel<<<dim3(512, 256), 256>>>(bias_table);
    pv_g<<<dim3(4, 256), 256>>>();
    ln_kernel<<<dim3(16384), 256>>>(gamma, beta, out);
}

// round 5
// speedup vs baseline: 3.6434x; 1.3439x over previous
#include <cuda_runtime.h>
#include <cstdint>

#define Hh 8
#define LN_EPS 1e-5f
#define SCALE 0.04419417382415922f  // 512^-0.5 (full C, as in source)

// ---------------- scratch (device globals) ----------------------------------
__device__ float g_x[(size_t)16384 * 512];       // tf32-rounded x
__device__ float g_w[(size_t)3 * 512 * 512];     // tf32-rounded wq|wk|wv
__device__ float g_q[(size_t)256 * 512 * 64];    // (b,h,l,d) tf32-rounded
__device__ float g_k[(size_t)256 * 512 * 64];    // (b,h,l,d) tf32-rounded
__device__ float g_vt[(size_t)256 * 64 * 512];   // (b,h,d,l) tf32-rounded
__device__ float g_preln[(size_t)16384 * 512];

// ---------------- helpers ---------------------------------------------------
__device__ __forceinline__ uint32_t s2u(const void* p) {
    uint32_t a;
    asm("{ .reg .u64 t; cvta.to.shared.u64 t, %1; cvt.u32.u64 %0, t; }" : "=r"(a) : "l"(p));
    return a;
}
__device__ __forceinline__ float rna_tf32(float v) {
    uint32_t t; asm("cvt.rna.tf32.f32 %0, %1;" : "=r"(t) : "f"(v));
    return __uint_as_float(t);
}
__device__ __forceinline__ void cpa16(uint32_t s, const void* g) {
    asm volatile("cp.async.cg.shared.global [%0], [%1], 16;" :: "r"(s), "l"(g));
}
__device__ __forceinline__ void cpa_commit() { asm volatile("cp.async.commit_group;" ::: "memory"); }
template <int N>
__device__ __forceinline__ void cpa_wait() { asm volatile("cp.async.wait_group %0;" :: "n"(N) : "memory"); }

__device__ __forceinline__ void ldm4(uint32_t (&r)[4], uint32_t addr) {
    asm volatile("ldmatrix.sync.aligned.m8n8.x4.shared.b16 {%0,%1,%2,%3}, [%4];"
                 : "=r"(r[0]), "=r"(r[1]), "=r"(r[2]), "=r"(r[3]) : "r"(addr));
}
__device__ __forceinline__ void mma8(float (&c)[4], const uint32_t (&a)[4], const uint32_t* b) {
    asm volatile(
        "mma.sync.aligned.m16n8k8.row.col.f32.tf32.tf32.f32 "
        "{%0,%1,%2,%3}, {%4,%5,%6,%7}, {%8,%9}, {%0,%1,%2,%3};"
        : "+f"(c[0]), "+f"(c[1]), "+f"(c[2]), "+f"(c[3])
        : "r"(a[0]), "r"(a[1]), "r"(a[2]), "r"(a[3]), "r"(b[0]), "r"(b[1]));
}

// ---------------- Kernel 0: tf32 pre-round of x and weights ------------------
__global__ __launch_bounds__(256) void cvt_all_kernel(
    const float* __restrict__ x, const float* __restrict__ wq,
    const float* __restrict__ wk, const float* __restrict__ wv)
{
    int idx = blockIdx.x * 256 + threadIdx.x;  // float4 index
    const int XF4 = 16384 * 512 / 4;
    const int WF4 = 512 * 512 / 4;
    float4 v; float* dst;
    if (idx < XF4) {
        v = ((const float4*)x)[idx];
        dst = (float*)&((float4*)g_x)[idx];
    } else {
        int j = idx - XF4;
        int w = j / WF4, r = j - w * WF4;
        const float* src = (w == 0) ? wq : (w == 1) ? wk : wv;
        v = ((const float4*)src)[r];
        dst = (float*)&((float4*)g_w)[(size_t)w * WF4 + r];
    }
    float4 o;
    o.x = rna_tf32(v.x); o.y = rna_tf32(v.y); o.z = rna_tf32(v.z); o.w = rna_tf32(v.w);
    *(float4*)dst = o;
}

// ---------------- Kernel 1: QKV projection (tf32 mma + ldmatrix) -------------
// CTA 128x128, 8 warps (2m x 4n), warp tile 64x32. K-chunk 32, double buffer.
// grid (4 n-tiles, 128 m-tiles, 3). Output (b,h,l,d); V transposed to (b,h,d,l).
#define QKV_SMEM 73728
__global__ __launch_bounds__(256, 2) void qkv_g(void)
{
    extern __shared__ float smem[];
    const uint32_t sb = s2u(smem);
    const int tid = threadIdx.x;
    const int lane = tid & 31, warp = tid >> 5;
    const int wm = warp & 1, wn = warp >> 1;
    const int g = lane >> 2, t4 = lane & 3;
    const int which = blockIdx.z;
    const int m0 = blockIdx.y * 128;
    const int n0 = blockIdx.x * 128;

    const float* __restrict__ A = g_x + (size_t)m0 * 512;
    const float* __restrict__ B = g_w + (size_t)which * 262144 + (size_t)n0 * 512;

    constexpr int A_F = 128 * 36;         // 4608 floats
    constexpr int STAGE = 2 * A_F;        // 9216 floats

    // per-thread ldmatrix offsets (bytes)
    const uint32_t a_off = (uint32_t)(((wm * 64 + (lane & 7) + ((lane >> 3) & 1) * 8) * 36
                                      + (lane >> 4) * 4) * 4);
    const uint32_t b_off = (uint32_t)((((lane & 7) + (lane >> 4) * 8 + wn * 32) * 36
                                      + ((lane >> 3) & 1) * 4) * 4) + A_F * 4;

    float acc[4][4][4];
#pragma unroll
    for (int mi = 0; mi < 4; ++mi)
#pragma unroll
        for (int ni = 0; ni < 4; ++ni)
#pragma unroll
            for (int r = 0; r < 4; ++r) acc[mi][ni][r] = 0.f;

    auto load_chunk = [&](int c, int buf) {
        uint32_t base = sb + (uint32_t)(buf * STAGE * 4);
#pragma unroll
        for (int i = 0; i < 8; ++i) {
            int idx = tid + i * 256;
            if (idx < 1024) {
                int r = idx >> 3, sg = idx & 7;
                cpa16(base + (uint32_t)((r * 36 + sg * 4) * 4),
                      A + (size_t)r * 512 + c * 32 + sg * 4);
            } else {
                int j = idx - 1024;
                int r = j >> 3, sg = j & 7;
                cpa16(base + (uint32_t)(A_F * 4 + (r * 36 + sg * 4) * 4),
                      B + (size_t)r * 512 + c * 32 + sg * 4);
            }
        }
    };

    load_chunk(0, 0);
    cpa_commit();

    for (int c = 0; c < 16; ++c) {
        if (c + 1 < 16) load_chunk(c + 1, (c + 1) & 1);
        cpa_commit();
        cpa_wait<1>();
        __syncthreads();
        uint32_t sa = sb + (uint32_t)((c & 1) * STAGE * 4);
#pragma unroll
        for (int ks = 0; ks < 4; ++ks) {
            const int k = ks * 8;
            uint32_t af[4][4], bf0[4], bf1[4];
#pragma unroll
            for (int mi = 0; mi < 4; ++mi)
                ldm4(af[mi], sa + a_off + (uint32_t)((mi * 16 * 36 + k) * 4));
            ldm4(bf0, sa + b_off + (uint32_t)(k * 4));
            ldm4(bf1, sa + b_off + (uint32_t)((16 * 36 + k) * 4));
#pragma unroll
            for (int mi = 0; mi < 4; ++mi) {
                mma8(acc[mi][0], af[mi], &bf0[0]);
                mma8(acc[mi][1], af[mi], &bf0[2]);
                mma8(acc[mi][2], af[mi], &bf1[0]);
                mma8(acc[mi][3], af[mi], &bf1[2]);
            }
        }
        __syncthreads();
    }

    if (which <= 1) {
        float* out = (which == 0) ? g_q : g_k;
#pragma unroll
        for (int mi = 0; mi < 4; ++mi) {
#pragma unroll
            for (int ni = 0; ni < 4; ++ni) {
                int n = n0 + wn * 32 + ni * 8 + 2 * t4;
                int h = n >> 6, d = n & 63;
                int m = m0 + wm * 64 + mi * 16 + g;
                int b = m >> 9, l = m & 511;
                float2 v0 = make_float2(rna_tf32(acc[mi][ni][0]), rna_tf32(acc[mi][ni][1]));
                float2 v1 = make_float2(rna_tf32(acc[mi][ni][2]), rna_tf32(acc[mi][ni][3]));
                *(float2*)&out[(((size_t)(b * 8 + h)) * 512 + l) * 64 + d] = v0;
                *(float2*)&out[(((size_t)(b * 8 + h)) * 512 + l + 8) * 64 + d] = v1;
            }
        }
    } else {
        // V: transpose through smem, write (b,h,d,l)
        float* sT = smem;  // 128 x 132
#pragma unroll
        for (int mi = 0; mi < 4; ++mi) {
#pragma unroll
            for (int ni = 0; ni < 4; ++ni) {
                int nl = wn * 32 + ni * 8 + 2 * t4;
                int ml = wm * 64 + mi * 16 + g;
                sT[nl * 132 + ml]           = rna_tf32(acc[mi][ni][0]);
                sT[(nl + 1) * 132 + ml]     = rna_tf32(acc[mi][ni][1]);
                sT[nl * 132 + ml + 8]       = rna_tf32(acc[mi][ni][2]);
                sT[(nl + 1) * 132 + ml + 8] = rna_tf32(acc[mi][ni][3]);
            }
        }
        __syncthreads();
        int b = m0 >> 9, l0 = m0 & 511;
#pragma unroll
        for (int i = 0; i < 16; ++i) {
            int f = tid + i * 256;
            int row = f >> 5, c4 = f & 31;
            float4 v = *(const float4*)&sT[row * 132 + c4 * 4];
            int n = n0 + row, h = n >> 6, d = n & 63;
            *(float4*)&g_vt[(((size_t)(b * 8 + h)) * 64 + d) * 512 + l0 + c4 * 4] = v;
        }
    }
}

// ---------------- Kernel 2: fused attention ----------------------------------
// CTA = (qb in [0,8), bh in [0,256)). 64 q-rows per CTA, two-pass over S in smem.
//   pass A: S = Q K^T * scale  (4 key-chunks of 128, cp.async double buffer)
//   pass B: row softmax + post-softmax rel-bias, rounded to tf32, in-place
//   pass C: O = P V           (4 l-chunks of 128 from transposed V)
// smem floats: sQ 64x68 | sS 64x516 | sKV 2x8704 | sbias 1024  = 55808 (223232B)
#define ATT_SMEM 223232
#define SQ_OFF   0
#define SS_OFF   4352
#define SKV_OFF  37376
#define SB_OFF   54784
__global__ __launch_bounds__(256, 1) void attn_g(const float* __restrict__ bias_table)
{
    extern __shared__ float smem[];
    const uint32_t sb = s2u(smem);
    const int tid = threadIdx.x;
    const int lane = tid & 31, warp = tid >> 5;
    const int wm = warp & 1, wn = warp >> 1;
    const int g = lane >> 2, t4 = lane & 3;
    const int qb = blockIdx.x;
    const int bh = blockIdx.y;
    const int b = bh >> 3, h = bh & 7;

    const float* __restrict__ gq = g_q + (size_t)bh * 32768 + (size_t)qb * 64 * 64;
    const float* __restrict__ gk = g_k + (size_t)bh * 32768;
    const float* __restrict__ gvt = g_vt + (size_t)bh * 32768;

    const uint32_t sQb = sb + SQ_OFF * 4;
    const uint32_t sSb = sb + SS_OFF * 4;
    const uint32_t sKVb = sb + SKV_OFF * 4;
    float* sS = smem + SS_OFF;
    float* sbias = smem + SB_OFF;

    // ---- load Q (64x64, stride 68) + bias column h ----
    // FIX (R4 bug): 256 threads x 4 cp.async cover rows 0..63, col segments
    // (sg+4j)*4 for j=0..3 -> full 64 columns, no OOB rows.
    {
        int r = tid >> 2, sg = tid & 3;
#pragma unroll
        for (int j = 0; j < 4; ++j) {
            int cf = (sg + 4 * j) * 4;
            cpa16(sQb + (uint32_t)((r * 68 + cf) * 4), gq + (size_t)r * 64 + cf);
        }
    }
#pragma unroll
    for (int i = 0; i < 4; ++i) {
        int j = tid + i * 256;
        if (j < 1023) sbias[j] = bias_table[(size_t)j * 8 + h];
    }
    cpa_commit();

    // ---- pass A: S = Q K^T * scale ----
    auto load_k = [&](int c, int buf) {
        uint32_t base = sKVb + (uint32_t)(buf * 8704 * 4);
        const float* src = gk + (size_t)c * 128 * 64;
#pragma unroll
        for (int i = 0; i < 8; ++i) {
            int idx = tid + i * 256;
            int r = idx >> 4, sg = idx & 15;
            cpa16(base + (uint32_t)((r * 68 + sg * 4) * 4), src + (size_t)r * 64 + sg * 4);
        }
    };
    load_k(0, 0);
    cpa_commit();

    const uint32_t aq_off = (uint32_t)(((wm * 32 + (lane & 7) + ((lane >> 3) & 1) * 8) * 68
                                       + (lane >> 4) * 4) * 4);
    const uint32_t bk_off = (uint32_t)((((lane & 7) + (lane >> 4) * 8 + wn * 32) * 68
                                       + ((lane >> 3) & 1) * 4) * 4);

    for (int c = 0; c < 4; ++c) {
        if (c + 1 < 4) load_k(c + 1, (c + 1) & 1);
        cpa_commit();
        cpa_wait<1>();
        __syncthreads();
        uint32_t skb = sKVb + (uint32_t)((c & 1) * 8704 * 4);

        float acc[2][4][4];
#pragma unroll
        for (int mi = 0; mi < 2; ++mi)
#pragma unroll
            for (int ni = 0; ni < 4; ++ni)
#pragma unroll
                for (int r = 0; r < 4; ++r) acc[mi][ni][r] = 0.f;

#pragma unroll
        for (int ks = 0; ks < 8; ++ks) {
            const int k = ks * 8;
            uint32_t af[2][4], bf0[4], bf1[4];
            ldm4(af[0], sQb + aq_off + (uint32_t)(k * 4));
            ldm4(af[1], sQb + aq_off + (uint32_t)((16 * 68 + k) * 4));
            ldm4(bf0, skb + bk_off + (uint32_t)(k * 4));
            ldm4(bf1, skb + bk_off + (uint32_t)((16 * 68 + k) * 4));
#pragma unroll
            for (int mi = 0; mi < 2; ++mi) {
                mma8(acc[mi][0], af[mi], &bf0[0]);
                mma8(acc[mi][1], af[mi], &bf0[2]);
                mma8(acc[mi][2], af[mi], &bf1[0]);
                mma8(acc[mi][3], af[mi], &bf1[2]);
            }
        }
        // store scaled S chunk
#pragma unroll
        for (int mi = 0; mi < 2; ++mi) {
#pragma unroll
            for (int ni = 0; ni < 4; ++ni) {
                int ml = wm * 32 + mi * 16 + g;
                int col = c * 128 + wn * 32 + ni * 8 + 2 * t4;
                *(float2*)&sS[ml * 516 + col] =
                    make_float2(acc[mi][ni][0] * SCALE, acc[mi][ni][1] * SCALE);
                *(float2*)&sS[(ml + 8) * 516 + col] =
                    make_float2(acc[mi][ni][2] * SCALE, acc[mi][ni][3] * SCALE);
            }
        }
        __syncthreads();
    }

    // ---- kick off V chunk 0 prefetch (overwrites K area; pass A done) ----
    auto load_v = [&](int c, int buf) {
        uint32_t base = sKVb + (uint32_t)(buf * 8704 * 4);
        const float* src = gvt + (size_t)c * 128;   // rows d stride 512, cols lc0..+128
#pragma unroll
        for (int i = 0; i < 8; ++i) {
            int idx = tid + i * 256;
            int r = idx >> 5, sg = idx & 31;
            cpa16(base + (uint32_t)((r * 132 + sg * 4) * 4), src + (size_t)r * 512 + sg * 4);
        }
    };
    load_v(0, 0);
    cpa_commit();

    // ---- pass B: softmax + bias (warp handles 8 rows) ----
    {
        const int r0 = warp * 8;
#pragma unroll
        for (int rr = 0; rr < 8; ++rr) {
            const int r = r0 + rr;
            float* row = &sS[r * 516];
            float vals[16];
            float m = -1e30f;
#pragma unroll
            for (int jj = 0; jj < 16; ++jj) {
                vals[jj] = row[lane + 32 * jj];
                m = fmaxf(m, vals[jj]);
            }
#pragma unroll
            for (int o = 16; o > 0; o >>= 1) m = fmaxf(m, __shfl_xor_sync(0xffffffffu, m, o));
            float s = 0.f;
#pragma unroll
            for (int jj = 0; jj < 16; ++jj) {
                vals[jj] = __expf(vals[jj] - m);
                s += vals[jj];
            }
#pragma unroll
            for (int o = 16; o > 0; o >>= 1) s += __shfl_xor_sync(0xffffffffu, s, o);
            float inv = 1.f / s;
            int bbase = 511 - (qb * 64 + r);
#pragma unroll
            for (int jj = 0; jj < 16; ++jj) {
                int col = lane + 32 * jj;
                row[col] = rna_tf32(vals[jj] * inv + sbias[bbase + col]);
            }
        }
    }
    __syncthreads();

    // ---- pass C: O = P V ----
    const uint32_t ap_off = (uint32_t)(((wm * 32 + (lane & 7) + ((lane >> 3) & 1) * 8) * 516
                                       + (lane >> 4) * 4) * 4);
    const uint32_t bv_off = (uint32_t)((((lane & 7) + (lane >> 4) * 8 + wn * 16) * 132
                                       + ((lane >> 3) & 1) * 4) * 4);
    float accO[2][2][4];
#pragma unroll
    for (int mi = 0; mi < 2; ++mi)
#pragma unroll
        for (int ni = 0; ni < 2; ++ni)
#pragma unroll
            for (int r = 0; r < 4; ++r) accO[mi][ni][r] = 0.f;

    for (int c = 0; c < 4; ++c) {
        if (c + 1 < 4) load_v(c + 1, (c + 1) & 1);
        cpa_commit();
        cpa_wait<1>();
        __syncthreads();
        uint32_t svb = sKVb + (uint32_t)((c & 1) * 8704 * 4);

#pragma unroll
        for (int ks = 0; ks < 16; ++ks) {
            const int k = ks * 8;
            const int kg = c * 128 + k;
            uint32_t af[2][4], bf[4];
            ldm4(af[0], sSb + ap_off + (uint32_t)(kg * 4));
            ldm4(af[1], sSb + ap_off + (uint32_t)((16 * 516 + kg) * 4));
            ldm4(bf, svb + bv_off + (uint32_t)(k * 4));
#pragma unroll
            for (int mi = 0; mi < 2; ++mi) {
                mma8(accO[mi][0], af[mi], &bf[0]);
                mma8(accO[mi][1], af[mi], &bf[2]);
            }
        }
        __syncthreads();
    }

    // epilogue: write O to preln (b, l, c)
#pragma unroll
    for (int mi = 0; mi < 2; ++mi) {
#pragma unroll
        for (int ni = 0; ni < 2; ++ni) {
            int m = wm * 32 + mi * 16 + g;
            int n = wn * 16 + ni * 8 + 2 * t4;
            size_t rowg = (size_t)(b * 512 + qb * 64 + m);
            *(float2*)&g_preln[rowg * 512 + h * 64 + n] =
                make_float2(accO[mi][ni][0], accO[mi][ni][1]);
            *(float2*)&g_preln[(rowg + 8) * 512 + h * 64 + n] =
                make_float2(accO[mi][ni][2], accO[mi][ni][3]);
        }
    }
}

// ---------------- Kernel 3: LayerNorm ----------------------------------------
__global__ __launch_bounds__(256) void ln_kernel(
    const float* __restrict__ gamma, const float* __restrict__ beta,
    float* __restrict__ out)
{
    const int row = blockIdx.x;
    const float* __restrict__ pr = g_preln + (size_t)row * 512;
    const int t = threadIdx.x;

    float v0 = pr[t], v1 = pr[t + 256];
    __shared__ float red[8];

    float s = v0 + v1;
#pragma unroll
    for (int o = 16; o > 0; o >>= 1) s += __shfl_xor_sync(0xffffffffu, s, o);
    if ((t & 31) == 0) red[t >> 5] = s;
    __syncthreads();
    float tot = red[0];
#pragma unroll
    for (int i = 1; i < 8; i++) tot += red[i];
    float mu = tot * (1.f / 512.f);

    float d0 = v0 - mu, d1 = v1 - mu;
    float sq = d0 * d0 + d1 * d1;
    __syncthreads();
#pragma unroll
    for (int o = 16; o > 0; o >>= 1) sq += __shfl_xor_sync(0xffffffffu, sq, o);
    if ((t & 31) == 0) red[t >> 5] = sq;
    __syncthreads();
    float totsq = red[0];
#pragma unroll
    for (int i = 1; i < 8; i++) totsq += red[i];
    float var = totsq * (1.f / 512.f);
    float inv = rsqrtf(var + LN_EPS);

    out[(size_t)row * 512 + t]       = gamma[t]       * d0 * inv + beta[t];
    out[(size_t)row * 512 + t + 256] = gamma[t + 256] * d1 * inv + beta[t + 256];
}

// ---------------------------------------------------------------------------
extern "C" void kernel_launch(void* const* d_in, const int* in_sizes, int n_in,
                              void* d_out, int out_size)
{
    const float* x          = (const float*)d_in[0];
    const float* wq         = (const float*)d_in[1];
    const float* wk         = (const float*)d_in[2];
    const float* wv         = (const float*)d_in[3];
    const float* bias_table = (const float*)d_in[4];
    const float* gamma      = (const float*)d_in[5];
    const float* beta       = (const float*)d_in[6];
    float* out = (float*)d_out;

    cudaFuncSetAttribute(qkv_g,  cudaFuncAttributeMaxDynamicSharedMemorySize, QKV_SMEM);
    cudaFuncSetAttribute(attn_g, cudaFuncAttributeMaxDynamicSharedMemorySize, ATT_SMEM);

    cvt_all_kernel<<<(2097152 + 3 * 65536) / 256, 256>>>(x, wq, wk, wv);
    qkv_g<<<dim3(4, 128, 3), 256, QKV_SMEM>>>();
    attn_g<<<dim3(8, 256), 256, ATT_SMEM>>>(bias_table);
    ln_kernel<<<dim3(16384), 256>>>(gamma, beta, out);
}

// round 6
// speedup vs baseline: 5.4191x; 1.4874x over previous
#include <cuda_runtime.h>
#include <cuda_fp16.h>
#include <cstdint>

#define Hh 8
#define LN_EPS 1e-5f
#define SCALE 0.04419417382415922f  // 512^-0.5 (full C, as in source)

// ---------------- scratch (device globals) ----------------------------------
__device__ __half g_xh[(size_t)16384 * 512];      // fp16 x
__device__ __half g_wh[(size_t)3 * 512 * 512];    // fp16 wq|wk|wv
__device__ __half g_qh[(size_t)256 * 512 * 64];   // (b,h,l,d)
__device__ __half g_kh[(size_t)256 * 512 * 64];   // (b,h,l,d)
__device__ __half g_vh[(size_t)256 * 64 * 512];   // (b,h,d,l) transposed V
__device__ float  g_preln[(size_t)16384 * 512];

// ---------------- helpers ---------------------------------------------------
__device__ __forceinline__ uint32_t s2u(const void* p) {
    uint32_t a;
    asm("{ .reg .u64 t; cvta.to.shared.u64 t, %1; cvt.u32.u64 %0, t; }" : "=r"(a) : "l"(p));
    return a;
}
__device__ __forceinline__ void cpa16(uint32_t s, const void* g) {
    asm volatile("cp.async.cg.shared.global [%0], [%1], 16;" :: "r"(s), "l"(g));
}
__device__ __forceinline__ void cpa_commit() { asm volatile("cp.async.commit_group;" ::: "memory"); }
template <int N>
__device__ __forceinline__ void cpa_wait() { asm volatile("cp.async.wait_group %0;" :: "n"(N) : "memory"); }

__device__ __forceinline__ void ldm4(uint32_t (&r)[4], uint32_t addr) {
    asm volatile("ldmatrix.sync.aligned.m8n8.x4.shared.b16 {%0,%1,%2,%3}, [%4];"
                 : "=r"(r[0]), "=r"(r[1]), "=r"(r[2]), "=r"(r[3]) : "r"(addr));
}
__device__ __forceinline__ void mma16(float (&c)[4], const uint32_t (&a)[4], const uint32_t* b) {
    asm volatile(
        "mma.sync.aligned.m16n8k16.row.col.f32.f16.f16.f32 "
        "{%0,%1,%2,%3}, {%4,%5,%6,%7}, {%8,%9}, {%0,%1,%2,%3};"
        : "+f"(c[0]), "+f"(c[1]), "+f"(c[2]), "+f"(c[3])
        : "r"(a[0]), "r"(a[1]), "r"(a[2]), "r"(a[3]), "r"(b[0]), "r"(b[1]));
}

// ---------------- Kernel 0: fp16 convert of x and weights --------------------
__global__ __launch_bounds__(256) void cvt_all_kernel(
    const float* __restrict__ x, const float* __restrict__ wq,
    const float* __restrict__ wk, const float* __restrict__ wv)
{
    int idx = blockIdx.x * 256 + threadIdx.x;   // 8-float group
    const int XG = 16384 * 512 / 8;             // 1048576
    const int WG = 512 * 512 / 8;               // 32768
    const float4* src; __half* dst;
    if (idx < XG) {
        src = (const float4*)x + (size_t)idx * 2;
        dst = g_xh + (size_t)idx * 8;
    } else {
        int j = idx - XG;
        int w = j / WG, r = j - w * WG;
        const float* s = (w == 0) ? wq : (w == 1) ? wk : wv;
        src = (const float4*)s + (size_t)r * 2;
        dst = g_wh + ((size_t)w * WG + r) * 8;
    }
    float4 a = src[0], b = src[1];
    __half2 h0 = __float22half2_rn(make_float2(a.x, a.y));
    __half2 h1 = __float22half2_rn(make_float2(a.z, a.w));
    __half2 h2 = __float22half2_rn(make_float2(b.x, b.y));
    __half2 h3 = __float22half2_rn(make_float2(b.z, b.w));
    uint4 o = make_uint4(*(uint32_t*)&h0, *(uint32_t*)&h1, *(uint32_t*)&h2, *(uint32_t*)&h3);
    *(uint4*)dst = o;
}

// ---------------- Kernel 1: QKV projection (fp16 mma m16n8k16) ---------------
// CTA 128x128, 8 warps (2m x 4n), warp tile 64x32. K-chunk 64, double buffer.
// grid (4 n-tiles, 128 m-tiles, 3). Output (b,h,l,d); V transposed to (b,h,d,l).
#define QKV_SMEM 73728
__global__ __launch_bounds__(256, 2) void qkv_g(void)
{
    extern __shared__ __half smh[];
    const uint32_t sb = s2u(smh);
    const int tid = threadIdx.x;
    const int lane = tid & 31, warp = tid >> 5;
    const int wm = warp & 1, wn = warp >> 1;
    const int g = lane >> 2, t4 = lane & 3;
    const int which = blockIdx.z;
    const int m0 = blockIdx.y * 128;
    const int n0 = blockIdx.x * 128;

    const __half* __restrict__ A = g_xh + (size_t)m0 * 512;
    const __half* __restrict__ B = g_wh + (size_t)which * 262144 + (size_t)n0 * 512;

    constexpr int A_H = 128 * 72;        // halves per A tile
    constexpr int STAGE_H = 2 * A_H;     // halves per stage (A+B)

    // ldmatrix per-thread byte offsets
    const uint32_t a_base = (uint32_t)(((wm * 64 + (lane & 15)) * 72 + (lane >> 4) * 8) * 2);
    const uint32_t b_base = (uint32_t)(A_H * 2 +
        (((lane & 7) + (lane >> 4) * 8 + wn * 32) * 72 + ((lane >> 3) & 1) * 8) * 2);

    float acc[4][4][4];
#pragma unroll
    for (int mi = 0; mi < 4; ++mi)
#pragma unroll
        for (int ni = 0; ni < 4; ++ni)
#pragma unroll
            for (int r = 0; r < 4; ++r) acc[mi][ni][r] = 0.f;

    auto load_chunk = [&](int c, int buf) {
        uint32_t base = sb + (uint32_t)(buf * STAGE_H * 2);
#pragma unroll
        for (int i = 0; i < 8; ++i) {
            int idx = tid + i * 256;
            if (idx < 1024) {
                int r = idx >> 3, sg = idx & 7;
                cpa16(base + (uint32_t)((r * 72 + sg * 8) * 2),
                      A + (size_t)r * 512 + c * 64 + sg * 8);
            } else {
                int j = idx - 1024;
                int r = j >> 3, sg = j & 7;
                cpa16(base + (uint32_t)(A_H * 2 + (r * 72 + sg * 8) * 2),
                      B + (size_t)r * 512 + c * 64 + sg * 8);
            }
        }
    };

    load_chunk(0, 0);
    cpa_commit();

    for (int c = 0; c < 8; ++c) {
        if (c + 1 < 8) load_chunk(c + 1, (c + 1) & 1);
        cpa_commit();
        cpa_wait<1>();
        __syncthreads();
        uint32_t sa = sb + (uint32_t)((c & 1) * STAGE_H * 2);
#pragma unroll
        for (int ks = 0; ks < 4; ++ks) {
            const uint32_t ko = (uint32_t)(ks * 32);   // 16 halves
            uint32_t af[4][4], bf0[4], bf1[4];
#pragma unroll
            for (int mi = 0; mi < 4; ++mi)
                ldm4(af[mi], sa + a_base + (uint32_t)(mi * 16 * 72 * 2) + ko);
            ldm4(bf0, sa + b_base + ko);
            ldm4(bf1, sa + b_base + (uint32_t)(16 * 72 * 2) + ko);
#pragma unroll
            for (int mi = 0; mi < 4; ++mi) {
                mma16(acc[mi][0], af[mi], &bf0[0]);
                mma16(acc[mi][1], af[mi], &bf0[2]);
                mma16(acc[mi][2], af[mi], &bf1[0]);
                mma16(acc[mi][3], af[mi], &bf1[2]);
            }
        }
        __syncthreads();
    }

    if (which <= 1) {
        __half* out = (which == 0) ? g_qh : g_kh;
#pragma unroll
        for (int mi = 0; mi < 4; ++mi) {
#pragma unroll
            for (int ni = 0; ni < 4; ++ni) {
                int n = n0 + wn * 32 + ni * 8 + 2 * t4;
                int h = n >> 6, d = n & 63;
                int m = m0 + wm * 64 + mi * 16 + g;
                int b = m >> 9, l = m & 511;
                __half2 v0 = __float22half2_rn(make_float2(acc[mi][ni][0], acc[mi][ni][1]));
                __half2 v1 = __float22half2_rn(make_float2(acc[mi][ni][2], acc[mi][ni][3]));
                *(__half2*)&out[(((size_t)(b * 8 + h)) * 512 + l) * 64 + d] = v0;
                *(__half2*)&out[(((size_t)(b * 8 + h)) * 512 + l + 8) * 64 + d] = v1;
            }
        }
    } else {
        // V: transpose through smem (half, stride 136), write (b,h,d,l)
        __half* sT = smh;
#pragma unroll
        for (int mi = 0; mi < 4; ++mi) {
#pragma unroll
            for (int ni = 0; ni < 4; ++ni) {
                int nl = wn * 32 + ni * 8 + 2 * t4;
                int ml = wm * 64 + mi * 16 + g;
                sT[nl * 136 + ml]           = __float2half_rn(acc[mi][ni][0]);
                sT[(nl + 1) * 136 + ml]     = __float2half_rn(acc[mi][ni][1]);
                sT[nl * 136 + ml + 8]       = __float2half_rn(acc[mi][ni][2]);
                sT[(nl + 1) * 136 + ml + 8] = __float2half_rn(acc[mi][ni][3]);
            }
        }
        __syncthreads();
        int b = m0 >> 9, l0 = m0 & 511;
#pragma unroll
        for (int i = 0; i < 8; ++i) {
            int f = tid + i * 256;
            int row = f >> 4, seg = f & 15;
            uint4 v = *(const uint4*)&sT[row * 136 + seg * 8];
            int n = n0 + row, h = n >> 6, d = n & 63;
            *(uint4*)&g_vh[(((size_t)(b * 8 + h)) * 64 + d) * 512 + l0 + seg * 8] = v;
        }
    }
}

// ---------------- Kernel 2: fused attention (fp16 mma) -----------------------
// CTA = (qb, bh). 64 q-rows, S fp32 resident in smem, P rewritten in-place fp16.
// bytes: Q 64x72h @0 (9216) | S 64x516f @9216 (132096) | KV 2x18432 @141312 | bias @178176 (4096)
#define ATT_SMEM 182272
__global__ __launch_bounds__(256, 1) void attn_g(const float* __restrict__ bias_table)
{
    extern __shared__ char smc[];
    const uint32_t sb = s2u(smc);
    const int tid = threadIdx.x;
    const int lane = tid & 31, warp = tid >> 5;
    const int wm = warp & 1, wn = warp >> 1;
    const int g = lane >> 2, t4 = lane & 3;
    const int qb = blockIdx.x;
    const int bh = blockIdx.y;
    const int b = bh >> 3, h = bh & 7;

    const __half* __restrict__ gq = g_qh + (size_t)bh * 32768 + (size_t)qb * 64 * 64;
    const __half* __restrict__ gk = g_kh + (size_t)bh * 32768;
    const __half* __restrict__ gv = g_vh + (size_t)bh * 32768;

    const uint32_t sQ = sb;
    const uint32_t sSb = sb + 9216;
    const uint32_t sKV = sb + 141312;
    float* sS = (float*)(smc + 9216);
    float* sbias = (float*)(smc + 178176);

    // ---- load Q (64x64 halves, stride 72) + bias column h ----
#pragma unroll
    for (int i = 0; i < 2; ++i) {
        int idx = tid + i * 256;
        int r = idx >> 3, sg = idx & 7;
        cpa16(sQ + (uint32_t)((r * 72 + sg * 8) * 2), gq + (size_t)r * 64 + sg * 8);
    }
#pragma unroll
    for (int i = 0; i < 4; ++i) {
        int j = tid + i * 256;
        if (j < 1023) sbias[j] = bias_table[(size_t)j * 8 + h];
    }
    cpa_commit();

    // ---- pass A: S = Q K^T * scale ----
    auto load_k = [&](int c, int buf) {
        uint32_t base = sKV + (uint32_t)(buf * 18432);
        const __half* src = gk + (size_t)c * 128 * 64;
#pragma unroll
        for (int i = 0; i < 4; ++i) {
            int idx = tid + i * 256;
            int r = idx >> 3, sg = idx & 7;
            cpa16(base + (uint32_t)((r * 72 + sg * 8) * 2), src + (size_t)r * 64 + sg * 8);
        }
    };
    load_k(0, 0);
    cpa_commit();

    const uint32_t aq_base = (uint32_t)(((wm * 32 + (lane & 15)) * 72 + (lane >> 4) * 8) * 2);
    const uint32_t bk_base = (uint32_t)((((lane & 7) + (lane >> 4) * 8 + wn * 32) * 72
                                        + ((lane >> 3) & 1) * 8) * 2);

    for (int c = 0; c < 4; ++c) {
        if (c + 1 < 4) load_k(c + 1, (c + 1) & 1);
        cpa_commit();
        cpa_wait<1>();
        __syncthreads();
        uint32_t skb = sKV + (uint32_t)((c & 1) * 18432);

        float acc[2][4][4];
#pragma unroll
        for (int mi = 0; mi < 2; ++mi)
#pragma unroll
            for (int ni = 0; ni < 4; ++ni)
#pragma unroll
                for (int r = 0; r < 4; ++r) acc[mi][ni][r] = 0.f;

#pragma unroll
        for (int ks = 0; ks < 4; ++ks) {
            const uint32_t ko = (uint32_t)(ks * 32);
            uint32_t af[2][4], bf0[4], bf1[4];
            ldm4(af[0], sQ + aq_base + ko);
            ldm4(af[1], sQ + aq_base + (uint32_t)(16 * 72 * 2) + ko);
            ldm4(bf0, skb + bk_base + ko);
            ldm4(bf1, skb + bk_base + (uint32_t)(16 * 72 * 2) + ko);
#pragma unroll
            for (int mi = 0; mi < 2; ++mi) {
                mma16(acc[mi][0], af[mi], &bf0[0]);
                mma16(acc[mi][1], af[mi], &bf0[2]);
                mma16(acc[mi][2], af[mi], &bf1[0]);
                mma16(acc[mi][3], af[mi], &bf1[2]);
            }
        }
#pragma unroll
        for (int mi = 0; mi < 2; ++mi) {
#pragma unroll
            for (int ni = 0; ni < 4; ++ni) {
                int ml = wm * 32 + mi * 16 + g;
                int col = c * 128 + wn * 32 + ni * 8 + 2 * t4;
                *(float2*)&sS[ml * 516 + col] =
                    make_float2(acc[mi][ni][0] * SCALE, acc[mi][ni][1] * SCALE);
                *(float2*)&sS[(ml + 8) * 516 + col] =
                    make_float2(acc[mi][ni][2] * SCALE, acc[mi][ni][3] * SCALE);
            }
        }
        __syncthreads();
    }

    // ---- prefetch V chunk 0 (KV area free) ----
    auto load_v = [&](int c, int buf) {
        uint32_t base = sKV + (uint32_t)(buf * 18432);
        const __half* src = gv + (size_t)c * 128;     // rows d (stride 512), l chunk
#pragma unroll
        for (int i = 0; i < 4; ++i) {
            int idx = tid + i * 256;
            int r = idx >> 4, sg = idx & 15;
            cpa16(base + (uint32_t)((r * 136 + sg * 8) * 2), src + (size_t)r * 512 + sg * 8);
        }
    };
    load_v(0, 0);
    cpa_commit();

    // ---- pass B: softmax + post-softmax bias; write P as fp16 in-place ----
    {
        const int r0 = warp * 8;
#pragma unroll
        for (int rr = 0; rr < 8; ++rr) {
            const int r = r0 + rr;
            float* row = &sS[r * 516];
            __half* rowh = (__half*)(smc + 9216) + (size_t)r * 1032;
            float vals[16];
            float m = -1e30f;
#pragma unroll
            for (int jj = 0; jj < 16; ++jj) {
                vals[jj] = row[lane + 32 * jj];
                m = fmaxf(m, vals[jj]);
            }
#pragma unroll
            for (int o = 16; o > 0; o >>= 1) m = fmaxf(m, __shfl_xor_sync(0xffffffffu, m, o));
            float s = 0.f;
#pragma unroll
            for (int jj = 0; jj < 16; ++jj) {
                vals[jj] = __expf(vals[jj] - m);
                s += vals[jj];
            }
#pragma unroll
            for (int o = 16; o > 0; o >>= 1) s += __shfl_xor_sync(0xffffffffu, s, o);
            float inv = 1.f / s;
            int bbase = 511 - (qb * 64 + r);
#pragma unroll
            for (int jj = 0; jj < 16; ++jj) {
                int col = lane + 32 * jj;
                rowh[col] = __float2half_rn(vals[jj] * inv + sbias[bbase + col]);
            }
        }
    }
    __syncthreads();

    // ---- pass C: O = P V (P fp16 rows pitch 1032 halves; V [d][l] stride 136) ----
    const uint32_t ap_base = sSb + (uint32_t)(((wm * 32 + (lane & 15)) * 1032 + (lane >> 4) * 8) * 2);
    const uint32_t bv_base = (uint32_t)((((lane & 7) + (lane >> 4) * 8 + wn * 16) * 136
                                        + ((lane >> 3) & 1) * 8) * 2);
    float accO[2][2][4];
#pragma unroll
    for (int mi = 0; mi < 2; ++mi)
#pragma unroll
        for (int ni = 0; ni < 2; ++ni)
#pragma unroll
            for (int r = 0; r < 4; ++r) accO[mi][ni][r] = 0.f;

    for (int c = 0; c < 4; ++c) {
        if (c + 1 < 4) load_v(c + 1, (c + 1) & 1);
        cpa_commit();
        cpa_wait<1>();
        __syncthreads();
        uint32_t svb = sKV + (uint32_t)((c & 1) * 18432);

#pragma unroll
        for (int ks = 0; ks < 8; ++ks) {
            const uint32_t kgo = (uint32_t)((c * 128 + ks * 16) * 2);
            const uint32_t ko = (uint32_t)(ks * 32);
            uint32_t af[2][4], bf[4];
            ldm4(af[0], ap_base + kgo);
            ldm4(af[1], ap_base + (uint32_t)(16 * 1032 * 2) + kgo);
            ldm4(bf, svb + bv_base + ko);
#pragma unroll
            for (int mi = 0; mi < 2; ++mi) {
                mma16(accO[mi][0], af[mi], &bf[0]);
                mma16(accO[mi][1], af[mi], &bf[2]);
            }
        }
        __syncthreads();
    }

    // epilogue: write O to preln (b, l, c)
#pragma unroll
    for (int mi = 0; mi < 2; ++mi) {
#pragma unroll
        for (int ni = 0; ni < 2; ++ni) {
            int m = wm * 32 + mi * 16 + g;
            int n = wn * 16 + ni * 8 + 2 * t4;
            size_t rowg = (size_t)(b * 512 + qb * 64 + m);
            *(float2*)&g_preln[rowg * 512 + h * 64 + n] =
                make_float2(accO[mi][ni][0], accO[mi][ni][1]);
            *(float2*)&g_preln[(rowg + 8) * 512 + h * 64 + n] =
                make_float2(accO[mi][ni][2], accO[mi][ni][3]);
        }
    }
}

// ---------------- Kernel 3: LayerNorm (2 rows/CTA, float4) -------------------
__global__ __launch_bounds__(256) void ln_kernel(
    const float* __restrict__ gamma, const float* __restrict__ beta,
    float* __restrict__ out)
{
    const int tid = threadIdx.x;
    const int row = blockIdx.x * 2 + (tid >> 7);
    const int ts = tid & 127;
    const int w = tid >> 5;
    const float* __restrict__ pr = g_preln + (size_t)row * 512;

    float4 v = *(const float4*)(pr + ts * 4);
    __shared__ float red[8], red2[8];

    float s = v.x + v.y + v.z + v.w;
#pragma unroll
    for (int o = 16; o > 0; o >>= 1) s += __shfl_xor_sync(0xffffffffu, s, o);
    if ((tid & 31) == 0) red[w] = s;
    __syncthreads();
    int wb = (w >> 2) * 4;
    float mu = (red[wb] + red[wb + 1] + red[wb + 2] + red[wb + 3]) * (1.f / 512.f);

    float d0 = v.x - mu, d1 = v.y - mu, d2 = v.z - mu, d3 = v.w - mu;
    float sq = d0 * d0 + d1 * d1 + d2 * d2 + d3 * d3;
#pragma unroll
    for (int o = 16; o > 0; o >>= 1) sq += __shfl_xor_sync(0xffffffffu, sq, o);
    if ((tid & 31) == 0) red2[w] = sq;
    __syncthreads();
    float var = (red2[wb] + red2[wb + 1] + red2[wb + 2] + red2[wb + 3]) * (1.f / 512.f);
    float inv = rsqrtf(var + LN_EPS);

    float4 gg = *(const float4*)(gamma + ts * 4);
    float4 bb = *(const float4*)(beta + ts * 4);
    float4 o;
    o.x = gg.x * d0 * inv + bb.x;
    o.y = gg.y * d1 * inv + bb.y;
    o.z = gg.z * d2 * inv + bb.z;
    o.w = gg.w * d3 * inv + bb.w;
    *(float4*)(out + (size_t)row * 512 + ts * 4) = o;
}

// ---------------------------------------------------------------------------
extern "C" void kernel_launch(void* const* d_in, const int* in_sizes, int n_in,
                              void* d_out, int out_size)
{
    const float* x          = (const float*)d_in[0];
    const float* wq         = (const float*)d_in[1];
    const float* wk         = (const float*)d_in[2];
    const float* wv         = (const float*)d_in[3];
    const float* bias_table = (const float*)d_in[4];
    const float* gamma      = (const float*)d_in[5];
    const float* beta       = (const float*)d_in[6];
    float* out = (float*)d_out;

    cudaFuncSetAttribute(qkv_g,  cudaFuncAttributeMaxDynamicSharedMemorySize, QKV_SMEM);
    cudaFuncSetAttribute(attn_g, cudaFuncAttributeMaxDynamicSharedMemorySize, ATT_SMEM);

    cvt_all_kernel<<<4480, 256>>>(x, wq, wk, wv);
    qkv_g<<<dim3(4, 128, 3), 256, QKV_SMEM>>>();
    attn_g<<<dim3(8, 256), 256, ATT_SMEM>>>(bias_table);
    ln_kernel<<<8192, 256>>>(gamma, beta, out);
}